// round 10
// baseline (speedup 1.0000x reference)
#include <cuda_runtime.h>
#include <cuda_bf16.h>
#include <math_constants.h>
#include <cfloat>

#define BATCH 8
#define NPTS 2500
#define NUM_PATCHES 25
#define PATCH_P 100
#define TOTAL_PTS (BATCH * NPTS)             // 20000
#define TOTAL_PATCHES (BATCH * NUM_PATCHES)  // 200

#define WPB 16                 // warps (=queries) per block
#define NSTEP_G 79             // ceil(2500/32)
#define NPAD_G (NSTEP_G * 32)  // 2528
#define NSTEP_P 4              // patch padded to 128
#define NSORT 4096             // presort bitonic size

#define GBLK_PER_B 157                      // ceil(2500/16)
#define GBLKS (GBLK_PER_B * BATCH)          // 1256
#define PBLKS (TOTAL_PTS / WPB)             // 1250
#define FUSED_BLKS (GBLKS + PBLKS)          // 2506

#define PAD_COORD 1.0e18f      // padded points: d^2 huge, never selected
#define BUFCAP 256             // per-warp candidate-index buffer (ushort)

__device__ float  g_cov_global[TOTAL_PTS * 6];
__device__ float  g_cov_patch[TOTAL_PTS * 6];
__device__ float4 g_sorted[BATCH][NPAD_G];   // x-sorted points, .w = orig idx bits

// ---------------------------------------------------------------------------
// 3x3 symmetric smallest-eigenvector (double), writes |v|.
// ---------------------------------------------------------------------------
__device__ __forceinline__ void smallest_evec_abs(
    const float* s, float out[3])
{
    double a00 = s[0], a01 = s[1], a02 = s[2];
    double a11 = s[3], a12 = s[4], a22 = s[5];

    double p1 = a01 * a01 + a02 * a02 + a12 * a12;
    double q  = (a00 + a11 + a22) * (1.0 / 3.0);
    double d0 = a00 - q, d1 = a11 - q, d2 = a22 - q;
    double p2 = d0 * d0 + d1 * d1 + d2 * d2 + 2.0 * p1;

    double lam;
    if (p2 <= 1e-300) {
        lam = q;
    } else {
        double p   = sqrt(p2 * (1.0 / 6.0));
        double inv = 1.0 / p;
        double b00 = d0 * inv, b11 = d1 * inv, b22 = d2 * inv;
        double b01 = a01 * inv, b02 = a02 * inv, b12 = a12 * inv;
        double detB = b00 * (b11 * b22 - b12 * b12)
                    - b01 * (b01 * b22 - b12 * b02)
                    + b02 * (b01 * b12 - b11 * b02);
        double r = 0.5 * detB;
        r = fmin(1.0, fmax(-1.0, r));
        double phi = acos(r) * (1.0 / 3.0);
        lam = q + 2.0 * p * cos(phi + 2.0943951023931953);
    }

    double r0x = a00 - lam, r0y = a01,       r0z = a02;
    double r1x = a01,       r1y = a11 - lam, r1z = a12;
    double r2x = a02,       r2y = a12,       r2z = a22 - lam;

    double c0x = r0y * r1z - r0z * r1y;
    double c0y = r0z * r1x - r0x * r1z;
    double c0z = r0x * r1y - r0y * r1x;

    double c1x = r0y * r2z - r0z * r2y;
    double c1y = r0z * r2x - r0x * r2z;
    double c1z = r0x * r2y - r0y * r2x;

    double c2x = r1y * r2z - r1z * r2y;
    double c2y = r1z * r2x - r1x * r2z;
    double c2z = r1x * r2y - r1y * r2x;

    double n0 = c0x * c0x + c0y * c0y + c0z * c0z;
    double n1 = c1x * c1x + c1y * c1y + c1z * c1z;
    double n2 = c2x * c2x + c2y * c2y + c2z * c2z;

    double vx = c0x, vy = c0y, vz = c0z, nn = n0;
    if (n1 > nn) { vx = c1x; vy = c1y; vz = c1z; nn = n1; }
    if (n2 > nn) { vx = c2x; vy = c2y; vz = c2z; nn = n2; }
    if (nn < 1e-300) { vx = 1.0; vy = 0.0; vz = 0.0; nn = 1.0; }

    double invn = rsqrt(nn);
    out[0] = (float)fabs(vx * invn);
    out[1] = (float)fabs(vy * invn);
    out[2] = (float)fabs(vz * invn);
}

// ascending bitonic sort of 32 floats across lanes
__device__ __forceinline__ float sort32f(float k, int lane)
{
    const unsigned FULL = 0xFFFFFFFFu;
#pragma unroll
    for (int size = 2; size <= 32; size <<= 1) {
#pragma unroll
        for (int stride = size >> 1; stride > 0; stride >>= 1) {
            float o = __shfl_xor_sync(FULL, k, stride);
            bool mn = ((lane & size) == 0) == ((lane & stride) == 0);
            k = mn ? fminf(k, o) : fmaxf(k, o);
        }
    }
    return k;
}

__device__ __forceinline__ float qdist2(float4 p, float qx, float qy, float qz)
{
    float dx = p.x - qx, dy = p.y - qy, dz = p.z - qz;
    return fmaf(dx, dx, fmaf(dy, dy, dz * dz));
}

// ---------------------------------------------------------------------------
// Process one 32-candidate chunk: update sorted-32 (v), tau, append buffer.
// All control warp-uniform.
// ---------------------------------------------------------------------------
template <int K>
__device__ __forceinline__ void process_chunk(
    const float4* __restrict__ sp, int base,
    float qx, float qy, float qz, int lane,
    float& v, float& tau, int& cnt, unsigned short* __restrict__ buf)
{
    const unsigned FULL = 0xFFFFFFFFu;
    float key = qdist2(sp[base + lane], qx, qy, qz);

    unsigned mask = __ballot_sync(FULL, key < tau);
    if (!mask) return;

    if (key < tau) {
        int off = cnt + __popc(mask & ((1u << lane) - 1u));
        if (off < BUFCAP) buf[off] = (unsigned short)(base + lane);
    }
    cnt += __popc(mask);

    if (__popc(mask) <= 8) {
        do {
            int src = __ffs(mask) - 1;
            mask &= mask - 1;
            float k  = __shfl_sync(FULL, key, src);
            float vp = __shfl_up_sync(FULL, v, 1);
            if (lane == 0) vp = -CUDART_INF_F;
            v = (v < k) ? v : ((vp < k) ? k : vp);
        } while (mask);
    } else {
        float s = sort32f(key, lane);
        float r = __shfl_sync(FULL, s, 31 - lane);
        v = fminf(v, r);
#pragma unroll
        for (int stride = 16; stride > 0; stride >>= 1) {
            float o = __shfl_xor_sync(FULL, v, stride);
            v = ((lane & stride) == 0) ? fminf(v, o) : fmaxf(v, o);
        }
    }
    tau = __shfl_sync(FULL, v, K - 1);
}

// Covariance accumulation + store (shared tail for both paths)
__device__ __forceinline__ void cov_reduce_store(
    float xx, float xy, float xz, float yy, float yz, float zz,
    int lane, float* __restrict__ cb)
{
    const unsigned FULL = 0xFFFFFFFFu;
#pragma unroll
    for (int off = 16; off > 0; off >>= 1) {
        xx += __shfl_xor_sync(FULL, xx, off);
        xy += __shfl_xor_sync(FULL, xy, off);
        xz += __shfl_xor_sync(FULL, xz, off);
        yy += __shfl_xor_sync(FULL, yy, off);
        yz += __shfl_xor_sync(FULL, yz, off);
        zz += __shfl_xor_sync(FULL, zz, off);
    }
    if (lane == 0) {
        cb[0] = xx; cb[1] = xy; cb[2] = xz;
        cb[3] = yy; cb[4] = yz; cb[5] = zz;
    }
}

// Gather covariance from buffered candidate indices (exact d^2 <= tau test)
__device__ __forceinline__ void cov_from_buffer(
    const float4* __restrict__ sp, const unsigned short* __restrict__ buf,
    int cnt, float qx, float qy, float qz, float tau, int lane,
    float* __restrict__ cb)
{
    float xx = 0.f, xy = 0.f, xz = 0.f, yy = 0.f, yz = 0.f, zz = 0.f;
    const int steps = (cnt + 31) >> 5;
    for (int s = 0; s < steps; ++s) {
        const int t = s * 32 + lane;
        if (t < cnt) {
            float4 p = sp[buf[t]];
            float d2 = qdist2(p, qx, qy, qz);
            if (d2 <= tau) {
                float dx = p.x - qx, dy = p.y - qy, dz = p.z - qz;
                xx = fmaf(dx, dx, xx);
                xy = fmaf(dx, dy, xy);
                xz = fmaf(dx, dz, xz);
                yy = fmaf(dy, dy, yy);
                yz = fmaf(dy, dz, yz);
                zz = fmaf(dz, dz, zz);
            }
        }
    }
    cov_reduce_store(xx, xy, xz, yy, yz, zz, lane, cb);
}

// Fallback: full rescan over nstep chunks (only if append buffer overflowed)
__device__ __forceinline__ void cov_from_rescan(
    const float4* __restrict__ sp, int nstep,
    float qx, float qy, float qz, float tau, int lane, float* __restrict__ cb)
{
    float xx = 0.f, xy = 0.f, xz = 0.f, yy = 0.f, yz = 0.f, zz = 0.f;
    for (int n = 0; n < nstep; ++n) {
        float4 p = sp[n * 32 + lane];
        float d2 = qdist2(p, qx, qy, qz);
        if (d2 <= tau) {
            float dx = p.x - qx, dy = p.y - qy, dz = p.z - qz;
            xx = fmaf(dx, dx, xx);
            xy = fmaf(dx, dy, xy);
            xz = fmaf(dx, dz, xz);
            yy = fmaf(dy, dy, yy);
            yz = fmaf(dy, dz, yz);
            zz = fmaf(dz, dz, zz);
        }
    }
    cov_reduce_store(xx, xy, xz, yy, yz, zz, lane, cb);
}

// ---------------------------------------------------------------------------
// Presort kernel: per batch, bitonic-sort points by x into g_sorted.
// Also zeroes the output accumulator.
// ---------------------------------------------------------------------------
__global__ void __launch_bounds__(512)
presort_kernel(const float* __restrict__ pc, float* __restrict__ out)
{
    __shared__ float2 pr[NSORT];   // 32 KB: (x, orig-index bits)

    const int b = blockIdx.x;
    const float* base = pc + (size_t)b * NPTS * 3;

    if (b == 0 && threadIdx.x == 0) out[0] = 0.0f;

    for (int i = threadIdx.x; i < NSORT; i += 512) {
        float x = (i < NPTS) ? base[3 * i] : FLT_MAX;
        pr[i] = make_float2(x, __int_as_float(i));
    }
    __syncthreads();

    for (int size = 2; size <= NSORT; size <<= 1) {
        for (int stride = size >> 1; stride > 0; stride >>= 1) {
            for (int t = threadIdx.x; t < NSORT / 2; t += 512) {
                int i = ((t / stride) * (stride << 1)) + (t % stride);
                int j = i + stride;
                bool asc = (i & size) == 0;
                float2 a = pr[i], c = pr[j];
                bool sw = asc ? (a.x > c.x) : (a.x < c.x);
                if (sw) { pr[i] = c; pr[j] = a; }
            }
            __syncthreads();
        }
    }

    for (int i = threadIdx.x; i < NPAD_G; i += 512) {
        float4 val = make_float4(PAD_COORD, PAD_COORD, PAD_COORD, 0.f);
        if (i < NPTS) {
            int idx = __float_as_int(pr[i].y);
            val = make_float4(base[3 * idx + 0], base[3 * idx + 1],
                              base[3 * idx + 2], __int_as_float(idx));
        }
        g_sorted[b][i] = val;
    }
}

// ---------------------------------------------------------------------------
// Fused kNN kernel. Blocks [0, GBLKS): global 32-NN on x-sorted points with
// outward chunk expansion + x-bound pruning. Rest: patch 16-NN (full scan).
// ---------------------------------------------------------------------------
__global__ void __launch_bounds__(512, 4)
knn_fused_kernel(const float* __restrict__ pc)
{
    __shared__ float4 sp[NPAD_G];                       // 40448 B
    __shared__ unsigned short abuf[WPB * BUFCAP];       //  8192 B

    const int warp = threadIdx.x >> 5;
    const int lane = threadIdx.x & 31;
    unsigned short* buf = abuf + warp * BUFCAP;

    if (blockIdx.x < GBLKS) {
        // -------- global 32-NN (x-sorted + pruned) --------
        const int b  = blockIdx.x / GBLK_PER_B;
        const int qb = blockIdx.x % GBLK_PER_B;

        for (int j = threadIdx.x; j < NPAD_G; j += 512)
            sp[j] = g_sorted[b][j];
        __syncthreads();

        const int q = qb * WPB + warp;      // sorted index
        if (q >= NPTS) return;

        const float4 qv = sp[q];
        const float qx = qv.x, qy = qv.y, qz = qv.z;
        const unsigned FULL = 0xFFFFFFFFu;

        // seed with own chunk
        const int cq = q >> 5;
        float k0 = qdist2(sp[(cq << 5) + lane], qx, qy, qz);
        buf[lane] = (unsigned short)((cq << 5) + lane);
        int cnt = 32;
        float v = sort32f(k0, lane);
        float tau = __shfl_sync(FULL, v, 31);

        // outward expansion with x-bound pruning (all warp-uniform)
        int cl = cq - 1, cr = cq + 1;
        bool goL = (cl >= 0), goR = (cr < NSTEP_G);
        while (goL || goR) {
            if (goL) {
                float xh = sp[(cl << 5) + 31].x;     // chunk's max x
                float dxx = qx - xh;                  // >= 0
                if (dxx * dxx > tau) {
                    goL = false;
                } else {
                    process_chunk<32>(sp, cl << 5, qx, qy, qz, lane,
                                      v, tau, cnt, buf);
                    if (--cl < 0) goL = false;
                }
            }
            if (goR) {
                float xl = sp[cr << 5].x;            // chunk's min x
                float dxx = xl - qx;                  // >= 0
                if (dxx * dxx > tau) {
                    goR = false;
                } else {
                    process_chunk<32>(sp, cr << 5, qx, qy, qz, lane,
                                      v, tau, cnt, buf);
                    if (++cr >= NSTEP_G) goR = false;
                }
            }
        }

        float* cb = g_cov_global
                  + (size_t)(b * NPTS + __float_as_int(qv.w)) * 6;
        if (cnt > BUFCAP)
            cov_from_rescan(sp, NSTEP_G, qx, qy, qz, tau, lane, cb);
        else
            cov_from_buffer(sp, buf, cnt, qx, qy, qz, tau, lane, cb);
    } else {
        // -------- patch 16-NN: 16 queries spanning <= 2 patches --------
        const int pblk = blockIdx.x - GBLKS;
        const int q0 = pblk * WPB;
        const int p0 = q0 / PATCH_P;

        for (int t = threadIdx.x; t < 256; t += 512) {
            const int which = t >> 7;
            const int local = t & 127;
            const int pp = p0 + which;
            float4 val = make_float4(PAD_COORD, PAD_COORD, PAD_COORD, 0.f);
            if (local < PATCH_P && pp < TOTAL_PATCHES) {
                const float* bb = pc + (size_t)pp * PATCH_P * 3;
                val = make_float4(bb[3 * local + 0], bb[3 * local + 1],
                                  bb[3 * local + 2], 0.f);
            }
            sp[(which << 7) + local] = val;
        }
        __syncthreads();

        const int gq = q0 + warp;
        const int pp = gq / PATCH_P;
        const int ql = gq % PATCH_P;
        const float4* spl = sp + ((pp - p0) << 7);

        const float4 qv = spl[ql];
        const float qx = qv.x, qy = qv.y, qz = qv.z;
        const unsigned FULL = 0xFFFFFFFFu;

        float k0 = qdist2(spl[lane], qx, qy, qz);
        buf[lane] = (unsigned short)lane;
        int cnt = 32;
        float v = sort32f(k0, lane);
        float tau = __shfl_sync(FULL, v, 15);
#pragma unroll
        for (int n = 1; n < NSTEP_P; ++n)
            process_chunk<16>(spl, n << 5, qx, qy, qz, lane, v, tau, cnt, buf);

        float* cb = g_cov_patch + (size_t)gq * 6;
        if (cnt > BUFCAP)
            cov_from_rescan(spl, NSTEP_P, qx, qy, qz, tau, lane, cb);
        else
            cov_from_buffer(spl, buf, cnt, qx, qy, qz, tau, lane, cb);
    }
}

// ---------------------------------------------------------------------------
// Loss: one eigen per thread (even: global, odd: patch), pair via shfl.
// ---------------------------------------------------------------------------
__global__ void __launch_bounds__(128)
loss_kernel(float* __restrict__ out)
{
    const int t = blockIdx.x * 128 + threadIdx.x;
    const int i = t >> 1;
    const int which = t & 1;

    float v = 0.0f;
    if (i < TOTAL_PTS) {
        const float* cb = which ? (g_cov_patch  + (size_t)i * 6)
                                : (g_cov_global + (size_t)i * 6);
        float nv[3];
        smallest_evec_abs(cb, nv);
        float ox = __shfl_xor_sync(0xFFFFFFFFu, nv[0], 1);
        float oy = __shfl_xor_sync(0xFFFFFFFFu, nv[1], 1);
        float oz = __shfl_xor_sync(0xFFFFFFFFu, nv[2], 1);
        if (which == 0) {
            float dx = ox - nv[0], dy = oy - nv[1], dz = oz - nv[2];
            v = sqrtf(fmaf(dx, dx, fmaf(dy, dy, dz * dz)));
        }
    }
#pragma unroll
    for (int off = 16; off > 0; off >>= 1)
        v += __shfl_down_sync(0xFFFFFFFFu, v, off);

    __shared__ float warpsum[4];
    const int lane = threadIdx.x & 31;
    const int wid  = threadIdx.x >> 5;
    if (lane == 0) warpsum[wid] = v;
    __syncthreads();

    if (wid == 0) {
        float s = (lane < 4) ? warpsum[lane] : 0.0f;
#pragma unroll
        for (int off = 2; off > 0; off >>= 1)
            s += __shfl_down_sync(0xFFFFFFFFu, s, off);
        if (lane == 0)
            atomicAdd(out, s * (1.0f / (float)TOTAL_PTS));
    }
}

// ---------------------------------------------------------------------------
extern "C" void kernel_launch(void* const* d_in, const int* in_sizes, int n_in,
                              void* d_out, int out_size)
{
    const float* pc = (const float*)d_in[0];
    float* out = (float*)d_out;

    presort_kernel<<<BATCH, 512>>>(pc, out);
    knn_fused_kernel<<<FUSED_BLKS, 512>>>(pc);
    loss_kernel<<<(2 * TOTAL_PTS + 127) / 128, 128>>>(out);
}

// round 11
// speedup vs baseline: 1.4714x; 1.4714x over previous
#include <cuda_runtime.h>
#include <cuda_bf16.h>
#include <math_constants.h>
#include <cfloat>

#define BATCH 8
#define NPTS 2500
#define NUM_PATCHES 25
#define PATCH_P 100
#define TOTAL_PTS (BATCH * NPTS)             // 20000
#define TOTAL_PATCHES (BATCH * NUM_PATCHES)  // 200

#define WPB 16                 // warps (=queries) per block
#define NSTEP_G 79             // ceil(2500/32)
#define NPAD_G (NSTEP_G * 32)  // 2528
#define NSTEP_P 4              // patch padded to 128
#define NBIN 1024              // counting-sort bins

#define GBLK_PER_B 157                      // ceil(2500/16)
#define GBLKS (GBLK_PER_B * BATCH)          // 1256
#define PBLKS (TOTAL_PTS / WPB)             // 1250
#define FUSED_BLKS (GBLKS + PBLKS)          // 2506

#define PAD_COORD 1.0e18f      // padded points: d^2 huge, never selected
#define BUFCAP 256             // per-warp candidate-index buffer (ushort)

__device__ float  g_cov_global[TOTAL_PTS * 6];
__device__ float  g_cov_patch[TOTAL_PTS * 6];
__device__ float4 g_sorted[BATCH][NPAD_G];   // bin-sorted points, .w = idx bits
__device__ float  g_binw[BATCH];             // conservative bin width

// ---------------------------------------------------------------------------
// 3x3 symmetric smallest-eigenvector (double), writes |v|.
// ---------------------------------------------------------------------------
__device__ __forceinline__ void smallest_evec_abs(
    const float* s, float out[3])
{
    double a00 = s[0], a01 = s[1], a02 = s[2];
    double a11 = s[3], a12 = s[4], a22 = s[5];

    double p1 = a01 * a01 + a02 * a02 + a12 * a12;
    double q  = (a00 + a11 + a22) * (1.0 / 3.0);
    double d0 = a00 - q, d1 = a11 - q, d2 = a22 - q;
    double p2 = d0 * d0 + d1 * d1 + d2 * d2 + 2.0 * p1;

    double lam;
    if (p2 <= 1e-300) {
        lam = q;
    } else {
        double p   = sqrt(p2 * (1.0 / 6.0));
        double inv = 1.0 / p;
        double b00 = d0 * inv, b11 = d1 * inv, b22 = d2 * inv;
        double b01 = a01 * inv, b02 = a02 * inv, b12 = a12 * inv;
        double detB = b00 * (b11 * b22 - b12 * b12)
                    - b01 * (b01 * b22 - b12 * b02)
                    + b02 * (b01 * b12 - b11 * b02);
        double r = 0.5 * detB;
        r = fmin(1.0, fmax(-1.0, r));
        double phi = acos(r) * (1.0 / 3.0);
        lam = q + 2.0 * p * cos(phi + 2.0943951023931953);
    }

    double r0x = a00 - lam, r0y = a01,       r0z = a02;
    double r1x = a01,       r1y = a11 - lam, r1z = a12;
    double r2x = a02,       r2y = a12,       r2z = a22 - lam;

    double c0x = r0y * r1z - r0z * r1y;
    double c0y = r0z * r1x - r0x * r1z;
    double c0z = r0x * r1y - r0y * r1x;

    double c1x = r0y * r2z - r0z * r2y;
    double c1y = r0z * r2x - r0x * r2z;
    double c1z = r0x * r2y - r0y * r2x;

    double c2x = r1y * r2z - r1z * r2y;
    double c2y = r1z * r2x - r1x * r2z;
    double c2z = r1x * r2y - r1y * r2x;

    double n0 = c0x * c0x + c0y * c0y + c0z * c0z;
    double n1 = c1x * c1x + c1y * c1y + c1z * c1z;
    double n2 = c2x * c2x + c2y * c2y + c2z * c2z;

    double vx = c0x, vy = c0y, vz = c0z, nn = n0;
    if (n1 > nn) { vx = c1x; vy = c1y; vz = c1z; nn = n1; }
    if (n2 > nn) { vx = c2x; vy = c2y; vz = c2z; nn = n2; }
    if (nn < 1e-300) { vx = 1.0; vy = 0.0; vz = 0.0; nn = 1.0; }

    double invn = rsqrt(nn);
    out[0] = (float)fabs(vx * invn);
    out[1] = (float)fabs(vy * invn);
    out[2] = (float)fabs(vz * invn);
}

// ascending bitonic sort of 32 floats across lanes
__device__ __forceinline__ float sort32f(float k, int lane)
{
    const unsigned FULL = 0xFFFFFFFFu;
#pragma unroll
    for (int size = 2; size <= 32; size <<= 1) {
#pragma unroll
        for (int stride = size >> 1; stride > 0; stride >>= 1) {
            float o = __shfl_xor_sync(FULL, k, stride);
            bool mn = ((lane & size) == 0) == ((lane & stride) == 0);
            k = mn ? fminf(k, o) : fmaxf(k, o);
        }
    }
    return k;
}

__device__ __forceinline__ float qdist2(float4 p, float qx, float qy, float qz)
{
    float dx = p.x - qx, dy = p.y - qy, dz = p.z - qz;
    return fmaf(dx, dx, fmaf(dy, dy, dz * dz));
}

// ---------------------------------------------------------------------------
// Process one 32-candidate chunk: update sorted-32 (v), tau, append buffer.
// ---------------------------------------------------------------------------
template <int K>
__device__ __forceinline__ void process_chunk(
    const float4* __restrict__ sp, int base,
    float qx, float qy, float qz, int lane,
    float& v, float& tau, int& cnt, unsigned short* __restrict__ buf)
{
    const unsigned FULL = 0xFFFFFFFFu;
    float key = qdist2(sp[base + lane], qx, qy, qz);

    unsigned mask = __ballot_sync(FULL, key < tau);
    if (!mask) return;

    if (key < tau) {
        int off = cnt + __popc(mask & ((1u << lane) - 1u));
        if (off < BUFCAP) buf[off] = (unsigned short)(base + lane);
    }
    cnt += __popc(mask);

    if (__popc(mask) <= 8) {
        do {
            int src = __ffs(mask) - 1;
            mask &= mask - 1;
            float k  = __shfl_sync(FULL, key, src);
            float vp = __shfl_up_sync(FULL, v, 1);
            if (lane == 0) vp = -CUDART_INF_F;
            v = (v < k) ? v : ((vp < k) ? k : vp);
        } while (mask);
    } else {
        float s = sort32f(key, lane);
        float r = __shfl_sync(FULL, s, 31 - lane);
        v = fminf(v, r);
#pragma unroll
        for (int stride = 16; stride > 0; stride >>= 1) {
            float o = __shfl_xor_sync(FULL, v, stride);
            v = ((lane & stride) == 0) ? fminf(v, o) : fmaxf(v, o);
        }
    }
    tau = __shfl_sync(FULL, v, K - 1);
}

__device__ __forceinline__ void cov_reduce_store(
    float xx, float xy, float xz, float yy, float yz, float zz,
    int lane, float* __restrict__ cb)
{
    const unsigned FULL = 0xFFFFFFFFu;
#pragma unroll
    for (int off = 16; off > 0; off >>= 1) {
        xx += __shfl_xor_sync(FULL, xx, off);
        xy += __shfl_xor_sync(FULL, xy, off);
        xz += __shfl_xor_sync(FULL, xz, off);
        yy += __shfl_xor_sync(FULL, yy, off);
        yz += __shfl_xor_sync(FULL, yz, off);
        zz += __shfl_xor_sync(FULL, zz, off);
    }
    if (lane == 0) {
        cb[0] = xx; cb[1] = xy; cb[2] = xz;
        cb[3] = yy; cb[4] = yz; cb[5] = zz;
    }
}

__device__ __forceinline__ void cov_from_buffer(
    const float4* __restrict__ sp, const unsigned short* __restrict__ buf,
    int cnt, float qx, float qy, float qz, float tau, int lane,
    float* __restrict__ cb)
{
    float xx = 0.f, xy = 0.f, xz = 0.f, yy = 0.f, yz = 0.f, zz = 0.f;
    const int steps = (cnt + 31) >> 5;
    for (int s = 0; s < steps; ++s) {
        const int t = s * 32 + lane;
        if (t < cnt) {
            float4 p = sp[buf[t]];
            float d2 = qdist2(p, qx, qy, qz);
            if (d2 <= tau) {
                float dx = p.x - qx, dy = p.y - qy, dz = p.z - qz;
                xx = fmaf(dx, dx, xx);
                xy = fmaf(dx, dy, xy);
                xz = fmaf(dx, dz, xz);
                yy = fmaf(dy, dy, yy);
                yz = fmaf(dy, dz, yz);
                zz = fmaf(dz, dz, zz);
            }
        }
    }
    cov_reduce_store(xx, xy, xz, yy, yz, zz, lane, cb);
}

__device__ __forceinline__ void cov_from_rescan(
    const float4* __restrict__ sp, int nstep,
    float qx, float qy, float qz, float tau, int lane, float* __restrict__ cb)
{
    float xx = 0.f, xy = 0.f, xz = 0.f, yy = 0.f, yz = 0.f, zz = 0.f;
    for (int n = 0; n < nstep; ++n) {
        float4 p = sp[n * 32 + lane];
        float d2 = qdist2(p, qx, qy, qz);
        if (d2 <= tau) {
            float dx = p.x - qx, dy = p.y - qy, dz = p.z - qz;
            xx = fmaf(dx, dx, xx);
            xy = fmaf(dx, dy, xy);
            xz = fmaf(dx, dz, xz);
            yy = fmaf(dy, dy, yy);
            yz = fmaf(dy, dz, yz);
            zz = fmaf(dz, dz, zz);
        }
    }
    cov_reduce_store(xx, xy, xz, yy, yz, zz, lane, cb);
}

// ---------------------------------------------------------------------------
// Presort: per batch, counting sort by quantized x (NBIN bins) into g_sorted.
// Points ordered by bin id; within-bin order arbitrary. Conservative bin
// width w (> true bin width) stored for exact pruning bounds.
// Also zeroes the output accumulator.
// ---------------------------------------------------------------------------
__global__ void __launch_bounds__(512)
presort_kernel(const float* __restrict__ pc, float* __restrict__ out)
{
    __shared__ int hist[NBIN];
    __shared__ int tmp[NBIN];
    __shared__ float redmin[16], redmax[16];

    const int b = blockIdx.x;
    const int tid = threadIdx.x;
    const int lane = tid & 31, wid = tid >> 5;
    const float* base = pc + (size_t)b * NPTS * 3;
    const unsigned FULL = 0xFFFFFFFFu;

    if (b == 0 && tid == 0) out[0] = 0.0f;

    // ---- min/max of x
    float mn = FLT_MAX, mx = -FLT_MAX;
    for (int i = tid; i < NPTS; i += 512) {
        float x = base[3 * i];
        mn = fminf(mn, x); mx = fmaxf(mx, x);
    }
#pragma unroll
    for (int off = 16; off > 0; off >>= 1) {
        mn = fminf(mn, __shfl_xor_sync(FULL, mn, off));
        mx = fmaxf(mx, __shfl_xor_sync(FULL, mx, off));
    }
    if (lane == 0) { redmin[wid] = mn; redmax[wid] = mx; }
    __syncthreads();
    if (tid < 32) {
        float a = (tid < 16) ? redmin[tid] : FLT_MAX;
        float c = (tid < 16) ? redmax[tid] : -FLT_MAX;
#pragma unroll
        for (int off = 8; off > 0; off >>= 1) {
            a = fminf(a, __shfl_xor_sync(FULL, a, off));
            c = fmaxf(c, __shfl_xor_sync(FULL, c, off));
        }
        if (tid == 0) { redmin[0] = a; redmax[0] = c; }
    }
    __syncthreads();
    mn = redmin[0]; mx = redmax[0];

    const float range = fmaxf(mx - mn, 1e-30f);
    const float scale = (float)NBIN / (range * 1.000002f);
    const float w     = range * (1.01f / (float)NBIN) + 1e-30f;  // > true width

    // ---- histogram
    for (int i = tid; i < NBIN; i += 512) hist[i] = 0;
    __syncthreads();
    for (int i = tid; i < NPTS; i += 512) {
        int bin = (int)((base[3 * i] - mn) * scale);
        bin = max(0, min(NBIN - 1, bin));
        atomicAdd(&hist[bin], 1);
    }
    __syncthreads();

    // ---- inclusive Hillis-Steele scan over NBIN
    for (int d = 1; d < NBIN; d <<= 1) {
        for (int i = tid; i < NBIN; i += 512)
            tmp[i] = hist[i] + ((i >= d) ? hist[i - d] : 0);
        __syncthreads();
        for (int i = tid; i < NBIN; i += 512) hist[i] = tmp[i];
        __syncthreads();
    }
    // exclusive offsets (as running counters) in tmp
    for (int i = tid; i < NBIN; i += 512) tmp[i] = (i > 0) ? hist[i - 1] : 0;
    __syncthreads();

    // ---- scatter
    for (int i = tid; i < NPTS; i += 512) {
        float x = base[3 * i + 0];
        float y = base[3 * i + 1];
        float z = base[3 * i + 2];
        int bin = (int)((x - mn) * scale);
        bin = max(0, min(NBIN - 1, bin));
        int pos = atomicAdd(&tmp[bin], 1);
        g_sorted[b][pos] = make_float4(x, y, z, __int_as_float(i));
    }
    for (int i = NPTS + tid; i < NPAD_G; i += 512)
        g_sorted[b][i] = make_float4(PAD_COORD, PAD_COORD, PAD_COORD, 0.f);

    if (tid == 0) g_binw[b] = w;
}

// ---------------------------------------------------------------------------
// Fused kNN kernel. Blocks [0, GBLKS): global 32-NN on bin-sorted points with
// outward chunk expansion + conservative x-bound pruning. Rest: patch 16-NN.
// ---------------------------------------------------------------------------
__global__ void __launch_bounds__(512, 4)
knn_fused_kernel(const float* __restrict__ pc)
{
    __shared__ float4 sp[NPAD_G];                       // 40448 B
    __shared__ unsigned short abuf[WPB * BUFCAP];       //  8192 B

    const int warp = threadIdx.x >> 5;
    const int lane = threadIdx.x & 31;
    unsigned short* buf = abuf + warp * BUFCAP;

    if (blockIdx.x < GBLKS) {
        // -------- global 32-NN (bin-sorted + pruned) --------
        const int b  = blockIdx.x / GBLK_PER_B;
        const int qb = blockIdx.x % GBLK_PER_B;
        const float w = g_binw[b];

        for (int j = threadIdx.x; j < NPAD_G; j += 512)
            sp[j] = g_sorted[b][j];
        __syncthreads();

        const int q = qb * WPB + warp;      // sorted position
        if (q >= NPTS) return;

        const float4 qv = sp[q];
        const float qx = qv.x, qy = qv.y, qz = qv.z;
        const unsigned FULL = 0xFFFFFFFFu;

        // seed with own chunk
        const int cq = q >> 5;
        float k0 = qdist2(sp[(cq << 5) + lane], qx, qy, qz);
        buf[lane] = (unsigned short)((cq << 5) + lane);
        int cnt = 32;
        float v = sort32f(k0, lane);
        float tau = __shfl_sync(FULL, v, 31);

        // outward expansion with conservative x-bound pruning
        int cl = cq - 1, cr = cq + 1;
        bool goL = (cl >= 0), goR = (cr < NSTEP_G);
        while (goL || goR) {
            if (goL) {
                // any element at position <= edge has x < x_edge + w
                float bnd = sp[(cl << 5) + 31].x + w;
                float dxx = fmaxf(qx - bnd, 0.0f);
                if (dxx * dxx > tau) {
                    goL = false;
                } else {
                    process_chunk<32>(sp, cl << 5, qx, qy, qz, lane,
                                      v, tau, cnt, buf);
                    if (--cl < 0) goL = false;
                }
            }
            if (goR) {
                // any element at position >= edge has x > x_edge - w
                float bnd = sp[cr << 5].x - w;
                float dxx = fmaxf(bnd - qx, 0.0f);
                if (dxx * dxx > tau) {
                    goR = false;
                } else {
                    process_chunk<32>(sp, cr << 5, qx, qy, qz, lane,
                                      v, tau, cnt, buf);
                    if (++cr >= NSTEP_G) goR = false;
                }
            }
        }

        float* cb = g_cov_global
                  + (size_t)(b * NPTS + __float_as_int(qv.w)) * 6;
        if (cnt > BUFCAP)
            cov_from_rescan(sp, NSTEP_G, qx, qy, qz, tau, lane, cb);
        else
            cov_from_buffer(sp, buf, cnt, qx, qy, qz, tau, lane, cb);
    } else {
        // -------- patch 16-NN: 16 queries spanning <= 2 patches --------
        const int pblk = blockIdx.x - GBLKS;
        const int q0 = pblk * WPB;
        const int p0 = q0 / PATCH_P;

        for (int t = threadIdx.x; t < 256; t += 512) {
            const int which = t >> 7;
            const int local = t & 127;
            const int pp = p0 + which;
            float4 val = make_float4(PAD_COORD, PAD_COORD, PAD_COORD, 0.f);
            if (local < PATCH_P && pp < TOTAL_PATCHES) {
                const float* bb = pc + (size_t)pp * PATCH_P * 3;
                val = make_float4(bb[3 * local + 0], bb[3 * local + 1],
                                  bb[3 * local + 2], 0.f);
            }
            sp[(which << 7) + local] = val;
        }
        __syncthreads();

        const int gq = q0 + warp;
        const int pp = gq / PATCH_P;
        const int ql = gq % PATCH_P;
        const float4* spl = sp + ((pp - p0) << 7);

        const float4 qv = spl[ql];
        const float qx = qv.x, qy = qv.y, qz = qv.z;
        const unsigned FULL = 0xFFFFFFFFu;

        float k0 = qdist2(spl[lane], qx, qy, qz);
        buf[lane] = (unsigned short)lane;
        int cnt = 32;
        float v = sort32f(k0, lane);
        float tau = __shfl_sync(FULL, v, 15);
#pragma unroll
        for (int n = 1; n < NSTEP_P; ++n)
            process_chunk<16>(spl, n << 5, qx, qy, qz, lane, v, tau, cnt, buf);

        float* cb = g_cov_patch + (size_t)gq * 6;
        if (cnt > BUFCAP)
            cov_from_rescan(spl, NSTEP_P, qx, qy, qz, tau, lane, cb);
        else
            cov_from_buffer(spl, buf, cnt, qx, qy, qz, tau, lane, cb);
    }
}

// ---------------------------------------------------------------------------
// Loss: one eigen per thread (even: global, odd: patch), pair via shfl.
// ---------------------------------------------------------------------------
__global__ void __launch_bounds__(128)
loss_kernel(float* __restrict__ out)
{
    const int t = blockIdx.x * 128 + threadIdx.x;
    const int i = t >> 1;
    const int which = t & 1;

    float v = 0.0f;
    if (i < TOTAL_PTS) {
        const float* cb = which ? (g_cov_patch  + (size_t)i * 6)
                                : (g_cov_global + (size_t)i * 6);
        float nv[3];
        smallest_evec_abs(cb, nv);
        float ox = __shfl_xor_sync(0xFFFFFFFFu, nv[0], 1);
        float oy = __shfl_xor_sync(0xFFFFFFFFu, nv[1], 1);
        float oz = __shfl_xor_sync(0xFFFFFFFFu, nv[2], 1);
        if (which == 0) {
            float dx = ox - nv[0], dy = oy - nv[1], dz = oz - nv[2];
            v = sqrtf(fmaf(dx, dx, fmaf(dy, dy, dz * dz)));
        }
    }
#pragma unroll
    for (int off = 16; off > 0; off >>= 1)
        v += __shfl_down_sync(0xFFFFFFFFu, v, off);

    __shared__ float warpsum[4];
    const int lane = threadIdx.x & 31;
    const int wid  = threadIdx.x >> 5;
    if (lane == 0) warpsum[wid] = v;
    __syncthreads();

    if (wid == 0) {
        float s = (lane < 4) ? warpsum[lane] : 0.0f;
#pragma unroll
        for (int off = 2; off > 0; off >>= 1)
            s += __shfl_down_sync(0xFFFFFFFFu, s, off);
        if (lane == 0)
            atomicAdd(out, s * (1.0f / (float)TOTAL_PTS));
    }
}

// ---------------------------------------------------------------------------
extern "C" void kernel_launch(void* const* d_in, const int* in_sizes, int n_in,
                              void* d_out, int out_size)
{
    const float* pc = (const float*)d_in[0];
    float* out = (float*)d_out;

    presort_kernel<<<BATCH, 512>>>(pc, out);
    knn_fused_kernel<<<FUSED_BLKS, 512>>>(pc);
    loss_kernel<<<(2 * TOTAL_PTS + 127) / 128, 128>>>(out);
}

// round 12
// speedup vs baseline: 1.5035x; 1.0218x over previous
#include <cuda_runtime.h>
#include <cuda_bf16.h>
#include <math_constants.h>
#include <cfloat>

#define BATCH 8
#define NPTS 2500
#define NUM_PATCHES 25
#define PATCH_P 100
#define TOTAL_PTS (BATCH * NPTS)             // 20000
#define TOTAL_PATCHES (BATCH * NUM_PATCHES)  // 200

#define WPB 16                 // warps (=queries) per block
#define NSTEP_G 79             // ceil(2500/32)
#define NPAD_G (NSTEP_G * 32)  // 2528
#define NSTEP_P 4              // patch padded to 128
#define NBIN 1024              // counting-sort bins

#define GBLK_PER_B 157                      // ceil(2500/16)
#define GBLKS (GBLK_PER_B * BATCH)          // 1256
#define PBLKS (TOTAL_PTS / WPB)             // 1250
#define FUSED_BLKS (GBLKS + PBLKS)          // 2506

#define PAD_COORD 1.0e18f      // padded points: d^2 huge, never selected
#define BUFCAP 256             // per-warp candidate-index buffer (ushort)

__device__ float  g_cov_global[TOTAL_PTS * 6];
__device__ float  g_cov_patch[TOTAL_PTS * 6];
__device__ float4 g_sorted[BATCH][NPAD_G];   // bin-sorted points, .w = idx bits
__device__ float  g_binw[BATCH];             // conservative bin width

// ---------------------------------------------------------------------------
// 3x3 symmetric smallest-eigenvector, writes |v|.
// Eigenvalue: float trig seed + 2 double Newton steps on the exact
// characteristic cubic (quadratic convergence -> double-precision lambda).
// Eigenvector: double cross-product of rows of (A - lam I).
// ---------------------------------------------------------------------------
__device__ __forceinline__ void smallest_evec_abs(
    const float* s, float out[3])
{
    double a00 = s[0], a01 = s[1], a02 = s[2];
    double a11 = s[3], a12 = s[4], a22 = s[5];

    double p1 = a01 * a01 + a02 * a02 + a12 * a12;
    double q  = (a00 + a11 + a22) * (1.0 / 3.0);
    double d0 = a00 - q, d1 = a11 - q, d2 = a22 - q;
    double p2 = d0 * d0 + d1 * d1 + d2 * d2 + 2.0 * p1;

    double lam;
    if (p2 <= 1e-300) {
        lam = q;
    } else {
        // ---- float seed (trig eigenvalue formula)
        float fa00 = s[0], fa01 = s[1], fa02 = s[2];
        float fa11 = s[3], fa12 = s[4], fa22 = s[5];
        float fq  = (fa00 + fa11 + fa22) * (1.0f / 3.0f);
        float fd0 = fa00 - fq, fd1 = fa11 - fq, fd2 = fa22 - fq;
        float fp1 = fa01 * fa01 + fa02 * fa02 + fa12 * fa12;
        float fp2 = fd0 * fd0 + fd1 * fd1 + fd2 * fd2 + 2.0f * fp1;
        float fp  = sqrtf(fmaxf(fp2, 1e-30f) * (1.0f / 6.0f));
        float fiv = 1.0f / fp;
        float b00 = fd0 * fiv, b11 = fd1 * fiv, b22 = fd2 * fiv;
        float b01 = fa01 * fiv, b02 = fa02 * fiv, b12 = fa12 * fiv;
        float detB = b00 * (b11 * b22 - b12 * b12)
                   - b01 * (b01 * b22 - b12 * b02)
                   + b02 * (b01 * b12 - b11 * b02);
        float fr = 0.5f * detB;
        fr = fminf(1.0f, fmaxf(-1.0f, fr));
        float phi = acosf(fr) * (1.0f / 3.0f);
        lam = (double)(fq + 2.0f * fp * cosf(phi + 2.0943951f));

        // ---- exact characteristic cubic: l^3 + c2 l^2 + c1 l + c0
        double c2 = -(a00 + a11 + a22);
        double m0 = a11 * a22 - a12 * a12;
        double m1 = a00 * a22 - a02 * a02;
        double m2 = a00 * a11 - a01 * a01;
        double c1 = m0 + m1 + m2;
        double det = a00 * m0
                   - a01 * (a01 * a22 - a12 * a02)
                   + a02 * (a01 * a12 - a11 * a02);
        double c0 = -det;

#pragma unroll
        for (int it = 0; it < 2; ++it) {
            double f  = ((lam + c2) * lam + c1) * lam + c0;
            double fp_ = (3.0 * lam + 2.0 * c2) * lam + c1;
            if (fabs(fp_) > 1e-300) lam -= f / fp_;
        }
    }

    double r0x = a00 - lam, r0y = a01,       r0z = a02;
    double r1x = a01,       r1y = a11 - lam, r1z = a12;
    double r2x = a02,       r2y = a12,       r2z = a22 - lam;

    double c0x = r0y * r1z - r0z * r1y;
    double c0y = r0z * r1x - r0x * r1z;
    double c0z = r0x * r1y - r0y * r1x;

    double c1x = r0y * r2z - r0z * r2y;
    double c1y = r0z * r2x - r0x * r2z;
    double c1z = r0x * r2y - r0y * r2x;

    double c2x = r1y * r2z - r1z * r2y;
    double c2y = r1z * r2x - r1x * r2z;
    double c2z = r1x * r2y - r1y * r2x;

    double n0 = c0x * c0x + c0y * c0y + c0z * c0z;
    double n1 = c1x * c1x + c1y * c1y + c1z * c1z;
    double n2 = c2x * c2x + c2y * c2y + c2z * c2z;

    double vx = c0x, vy = c0y, vz = c0z, nn = n0;
    if (n1 > nn) { vx = c1x; vy = c1y; vz = c1z; nn = n1; }
    if (n2 > nn) { vx = c2x; vy = c2y; vz = c2z; nn = n2; }
    if (nn < 1e-300) { vx = 1.0; vy = 0.0; vz = 0.0; nn = 1.0; }

    double invn = rsqrt(nn);
    out[0] = (float)fabs(vx * invn);
    out[1] = (float)fabs(vy * invn);
    out[2] = (float)fabs(vz * invn);
}

// ascending bitonic sort of 32 floats across lanes
__device__ __forceinline__ float sort32f(float k, int lane)
{
    const unsigned FULL = 0xFFFFFFFFu;
#pragma unroll
    for (int size = 2; size <= 32; size <<= 1) {
#pragma unroll
        for (int stride = size >> 1; stride > 0; stride >>= 1) {
            float o = __shfl_xor_sync(FULL, k, stride);
            bool mn = ((lane & size) == 0) == ((lane & stride) == 0);
            k = mn ? fminf(k, o) : fmaxf(k, o);
        }
    }
    return k;
}

__device__ __forceinline__ float qdist2(float4 p, float qx, float qy, float qz)
{
    float dx = p.x - qx, dy = p.y - qy, dz = p.z - qz;
    return fmaf(dx, dx, fmaf(dy, dy, dz * dz));
}

// ---------------------------------------------------------------------------
// Process one 32-candidate chunk: update sorted-32 (v), tau, append buffer.
// ---------------------------------------------------------------------------
template <int K>
__device__ __forceinline__ void process_chunk(
    const float4* __restrict__ sp, int base,
    float qx, float qy, float qz, int lane,
    float& v, float& tau, int& cnt, unsigned short* __restrict__ buf)
{
    const unsigned FULL = 0xFFFFFFFFu;
    float key = qdist2(sp[base + lane], qx, qy, qz);

    unsigned mask = __ballot_sync(FULL, key < tau);
    if (!mask) return;

    if (key < tau) {
        int off = cnt + __popc(mask & ((1u << lane) - 1u));
        if (off < BUFCAP) buf[off] = (unsigned short)(base + lane);
    }
    cnt += __popc(mask);

    if (__popc(mask) <= 8) {
        do {
            int src = __ffs(mask) - 1;
            mask &= mask - 1;
            float k  = __shfl_sync(FULL, key, src);
            float vp = __shfl_up_sync(FULL, v, 1);
            if (lane == 0) vp = -CUDART_INF_F;
            v = (v < k) ? v : ((vp < k) ? k : vp);
        } while (mask);
    } else {
        float s = sort32f(key, lane);
        float r = __shfl_sync(FULL, s, 31 - lane);
        v = fminf(v, r);
#pragma unroll
        for (int stride = 16; stride > 0; stride >>= 1) {
            float o = __shfl_xor_sync(FULL, v, stride);
            v = ((lane & stride) == 0) ? fminf(v, o) : fmaxf(v, o);
        }
    }
    tau = __shfl_sync(FULL, v, K - 1);
}

__device__ __forceinline__ void cov_reduce_store(
    float xx, float xy, float xz, float yy, float yz, float zz,
    int lane, float* __restrict__ cb)
{
    const unsigned FULL = 0xFFFFFFFFu;
#pragma unroll
    for (int off = 16; off > 0; off >>= 1) {
        xx += __shfl_xor_sync(FULL, xx, off);
        xy += __shfl_xor_sync(FULL, xy, off);
        xz += __shfl_xor_sync(FULL, xz, off);
        yy += __shfl_xor_sync(FULL, yy, off);
        yz += __shfl_xor_sync(FULL, yz, off);
        zz += __shfl_xor_sync(FULL, zz, off);
    }
    if (lane == 0) {
        cb[0] = xx; cb[1] = xy; cb[2] = xz;
        cb[3] = yy; cb[4] = yz; cb[5] = zz;
    }
}

__device__ __forceinline__ void cov_from_buffer(
    const float4* __restrict__ sp, const unsigned short* __restrict__ buf,
    int cnt, float qx, float qy, float qz, float tau, int lane,
    float* __restrict__ cb)
{
    float xx = 0.f, xy = 0.f, xz = 0.f, yy = 0.f, yz = 0.f, zz = 0.f;
    const int steps = (cnt + 31) >> 5;
    for (int s = 0; s < steps; ++s) {
        const int t = s * 32 + lane;
        if (t < cnt) {
            float4 p = sp[buf[t]];
            float d2 = qdist2(p, qx, qy, qz);
            if (d2 <= tau) {
                float dx = p.x - qx, dy = p.y - qy, dz = p.z - qz;
                xx = fmaf(dx, dx, xx);
                xy = fmaf(dx, dy, xy);
                xz = fmaf(dx, dz, xz);
                yy = fmaf(dy, dy, yy);
                yz = fmaf(dy, dz, yz);
                zz = fmaf(dz, dz, zz);
            }
        }
    }
    cov_reduce_store(xx, xy, xz, yy, yz, zz, lane, cb);
}

__device__ __forceinline__ void cov_from_rescan(
    const float4* __restrict__ sp, int nstep,
    float qx, float qy, float qz, float tau, int lane, float* __restrict__ cb)
{
    float xx = 0.f, xy = 0.f, xz = 0.f, yy = 0.f, yz = 0.f, zz = 0.f;
    for (int n = 0; n < nstep; ++n) {
        float4 p = sp[n * 32 + lane];
        float d2 = qdist2(p, qx, qy, qz);
        if (d2 <= tau) {
            float dx = p.x - qx, dy = p.y - qy, dz = p.z - qz;
            xx = fmaf(dx, dx, xx);
            xy = fmaf(dx, dy, xy);
            xz = fmaf(dx, dz, xz);
            yy = fmaf(dy, dy, yy);
            yz = fmaf(dy, dz, yz);
            zz = fmaf(dz, dz, zz);
        }
    }
    cov_reduce_store(xx, xy, xz, yy, yz, zz, lane, cb);
}

// ---------------------------------------------------------------------------
// Presort: per batch, counting sort by quantized x (NBIN bins) into g_sorted.
// 1024 threads; warp-shfl hierarchical scan (3 barriers total).
// Also zeroes the output accumulator.
// ---------------------------------------------------------------------------
__global__ void __launch_bounds__(1024)
presort_kernel(const float* __restrict__ pc, float* __restrict__ out)
{
    __shared__ int   hist[NBIN];
    __shared__ int   ctr[NBIN];
    __shared__ int   wsum[32];
    __shared__ float redmin[32], redmax[32];

    const int b = blockIdx.x;
    const int tid = threadIdx.x;
    const int lane = tid & 31, wid = tid >> 5;
    const float* base = pc + (size_t)b * NPTS * 3;
    const unsigned FULL = 0xFFFFFFFFu;

    if (b == 0 && tid == 0) out[0] = 0.0f;

    // ---- min/max of x + zero histogram
    hist[tid] = 0;
    float mn = FLT_MAX, mx = -FLT_MAX;
    for (int i = tid; i < NPTS; i += 1024) {
        float x = base[3 * i];
        mn = fminf(mn, x); mx = fmaxf(mx, x);
    }
#pragma unroll
    for (int off = 16; off > 0; off >>= 1) {
        mn = fminf(mn, __shfl_xor_sync(FULL, mn, off));
        mx = fmaxf(mx, __shfl_xor_sync(FULL, mx, off));
    }
    if (lane == 0) { redmin[wid] = mn; redmax[wid] = mx; }
    __syncthreads();
    if (tid < 32) {
        float a = redmin[tid], c = redmax[tid];
#pragma unroll
        for (int off = 16; off > 0; off >>= 1) {
            a = fminf(a, __shfl_xor_sync(FULL, a, off));
            c = fmaxf(c, __shfl_xor_sync(FULL, c, off));
        }
        if (tid == 0) { redmin[0] = a; redmax[0] = c; }
    }
    __syncthreads();
    mn = redmin[0]; mx = redmax[0];

    const float range = fmaxf(mx - mn, 1e-30f);
    const float scale = (float)NBIN / (range * 1.000002f);
    const float w     = range * (1.01f / (float)NBIN) + 1e-30f;  // > true width

    // ---- histogram (hist zeroed above, ordered by the two barriers)
    for (int i = tid; i < NPTS; i += 1024) {
        int bin = (int)((base[3 * i] - mn) * scale);
        bin = max(0, min(NBIN - 1, bin));
        atomicAdd(&hist[bin], 1);
    }
    __syncthreads();

    // ---- hierarchical scan: one bin per thread
    int c = hist[tid];
    int incl = c;
#pragma unroll
    for (int d = 1; d < 32; d <<= 1) {
        int o = __shfl_up_sync(FULL, incl, d);
        if (lane >= d) incl += o;
    }
    if (lane == 31) wsum[wid] = incl;
    __syncthreads();
    if (tid < 32) {
        int sv = wsum[tid];
#pragma unroll
        for (int d = 1; d < 32; d <<= 1) {
            int o = __shfl_up_sync(FULL, sv, d);
            if (tid >= d) sv += o;
        }
        wsum[tid] = sv;
    }
    __syncthreads();
    int offset = (wid > 0) ? wsum[wid - 1] : 0;
    ctr[tid] = offset + incl - c;   // exclusive prefix = scatter base
    __syncthreads();

    // ---- scatter
    for (int i = tid; i < NPTS; i += 1024) {
        float x = base[3 * i + 0];
        float y = base[3 * i + 1];
        float z = base[3 * i + 2];
        int bin = (int)((x - mn) * scale);
        bin = max(0, min(NBIN - 1, bin));
        int pos = atomicAdd(&ctr[bin], 1);
        g_sorted[b][pos] = make_float4(x, y, z, __int_as_float(i));
    }
    for (int i = NPTS + tid; i < NPAD_G; i += 1024)
        g_sorted[b][i] = make_float4(PAD_COORD, PAD_COORD, PAD_COORD, 0.f);

    if (tid == 0) g_binw[b] = w;
}

// ---------------------------------------------------------------------------
// Fused kNN kernel. Blocks [0, GBLKS): global 32-NN on bin-sorted points with
// outward chunk expansion + conservative x-bound pruning. Rest: patch 16-NN.
// ---------------------------------------------------------------------------
__global__ void __launch_bounds__(512, 4)
knn_fused_kernel(const float* __restrict__ pc)
{
    __shared__ float4 sp[NPAD_G];                       // 40448 B
    __shared__ unsigned short abuf[WPB * BUFCAP];       //  8192 B

    const int warp = threadIdx.x >> 5;
    const int lane = threadIdx.x & 31;
    unsigned short* buf = abuf + warp * BUFCAP;

    if (blockIdx.x < GBLKS) {
        // -------- global 32-NN (bin-sorted + pruned) --------
        const int b  = blockIdx.x / GBLK_PER_B;
        const int qb = blockIdx.x % GBLK_PER_B;
        const float w = g_binw[b];

        for (int j = threadIdx.x; j < NPAD_G; j += 512)
            sp[j] = g_sorted[b][j];
        __syncthreads();

        const int q = qb * WPB + warp;      // sorted position
        if (q >= NPTS) return;

        const float4 qv = sp[q];
        const float qx = qv.x, qy = qv.y, qz = qv.z;
        const unsigned FULL = 0xFFFFFFFFu;

        // seed with own chunk
        const int cq = q >> 5;
        float k0 = qdist2(sp[(cq << 5) + lane], qx, qy, qz);
        buf[lane] = (unsigned short)((cq << 5) + lane);
        int cnt = 32;
        float v = sort32f(k0, lane);
        float tau = __shfl_sync(FULL, v, 31);

        // outward expansion with conservative x-bound pruning
        int cl = cq - 1, cr = cq + 1;
        bool goL = (cl >= 0), goR = (cr < NSTEP_G);
        while (goL || goR) {
            if (goL) {
                float bnd = sp[(cl << 5) + 31].x + w;
                float dxx = fmaxf(qx - bnd, 0.0f);
                if (dxx * dxx > tau) {
                    goL = false;
                } else {
                    process_chunk<32>(sp, cl << 5, qx, qy, qz, lane,
                                      v, tau, cnt, buf);
                    if (--cl < 0) goL = false;
                }
            }
            if (goR) {
                float bnd = sp[cr << 5].x - w;
                float dxx = fmaxf(bnd - qx, 0.0f);
                if (dxx * dxx > tau) {
                    goR = false;
                } else {
                    process_chunk<32>(sp, cr << 5, qx, qy, qz, lane,
                                      v, tau, cnt, buf);
                    if (++cr >= NSTEP_G) goR = false;
                }
            }
        }

        float* cb = g_cov_global
                  + (size_t)(b * NPTS + __float_as_int(qv.w)) * 6;
        if (cnt > BUFCAP)
            cov_from_rescan(sp, NSTEP_G, qx, qy, qz, tau, lane, cb);
        else
            cov_from_buffer(sp, buf, cnt, qx, qy, qz, tau, lane, cb);
    } else {
        // -------- patch 16-NN: 16 queries spanning <= 2 patches --------
        const int pblk = blockIdx.x - GBLKS;
        const int q0 = pblk * WPB;
        const int p0 = q0 / PATCH_P;

        for (int t = threadIdx.x; t < 256; t += 512) {
            const int which = t >> 7;
            const int local = t & 127;
            const int pp = p0 + which;
            float4 val = make_float4(PAD_COORD, PAD_COORD, PAD_COORD, 0.f);
            if (local < PATCH_P && pp < TOTAL_PATCHES) {
                const float* bb = pc + (size_t)pp * PATCH_P * 3;
                val = make_float4(bb[3 * local + 0], bb[3 * local + 1],
                                  bb[3 * local + 2], 0.f);
            }
            sp[(which << 7) + local] = val;
        }
        __syncthreads();

        const int gq = q0 + warp;
        const int pp = gq / PATCH_P;
        const int ql = gq % PATCH_P;
        const float4* spl = sp + ((pp - p0) << 7);

        const float4 qv = spl[ql];
        const float qx = qv.x, qy = qv.y, qz = qv.z;
        const unsigned FULL = 0xFFFFFFFFu;

        float k0 = qdist2(spl[lane], qx, qy, qz);
        buf[lane] = (unsigned short)lane;
        int cnt = 32;
        float v = sort32f(k0, lane);
        float tau = __shfl_sync(FULL, v, 15);
#pragma unroll
        for (int n = 1; n < NSTEP_P; ++n)
            process_chunk<16>(spl, n << 5, qx, qy, qz, lane, v, tau, cnt, buf);

        float* cb = g_cov_patch + (size_t)gq * 6;
        if (cnt > BUFCAP)
            cov_from_rescan(spl, NSTEP_P, qx, qy, qz, tau, lane, cb);
        else
            cov_from_buffer(spl, buf, cnt, qx, qy, qz, tau, lane, cb);
    }
}

// ---------------------------------------------------------------------------
// Loss: one eigen per thread (even: global, odd: patch), pair via shfl.
// ---------------------------------------------------------------------------
__global__ void __launch_bounds__(128)
loss_kernel(float* __restrict__ out)
{
    const int t = blockIdx.x * 128 + threadIdx.x;
    const int i = t >> 1;
    const int which = t & 1;

    float v = 0.0f;
    if (i < TOTAL_PTS) {
        const float* cb = which ? (g_cov_patch  + (size_t)i * 6)
                                : (g_cov_global + (size_t)i * 6);
        float nv[3];
        smallest_evec_abs(cb, nv);
        float ox = __shfl_xor_sync(0xFFFFFFFFu, nv[0], 1);
        float oy = __shfl_xor_sync(0xFFFFFFFFu, nv[1], 1);
        float oz = __shfl_xor_sync(0xFFFFFFFFu, nv[2], 1);
        if (which == 0) {
            float dx = ox - nv[0], dy = oy - nv[1], dz = oz - nv[2];
            v = sqrtf(fmaf(dx, dx, fmaf(dy, dy, dz * dz)));
        }
    }
#pragma unroll
    for (int off = 16; off > 0; off >>= 1)
        v += __shfl_down_sync(0xFFFFFFFFu, v, off);

    __shared__ float warpsum[4];
    const int lane = threadIdx.x & 31;
    const int wid  = threadIdx.x >> 5;
    if (lane == 0) warpsum[wid] = v;
    __syncthreads();

    if (wid == 0) {
        float s = (lane < 4) ? warpsum[lane] : 0.0f;
#pragma unroll
        for (int off = 2; off > 0; off >>= 1)
            s += __shfl_down_sync(0xFFFFFFFFu, s, off);
        if (lane == 0)
            atomicAdd(out, s * (1.0f / (float)TOTAL_PTS));
    }
}

// ---------------------------------------------------------------------------
extern "C" void kernel_launch(void* const* d_in, const int* in_sizes, int n_in,
                              void* d_out, int out_size)
{
    const float* pc = (const float*)d_in[0];
    float* out = (float*)d_out;

    presort_kernel<<<BATCH, 1024>>>(pc, out);
    knn_fused_kernel<<<FUSED_BLKS, 512>>>(pc);
    loss_kernel<<<(2 * TOTAL_PTS + 127) / 128, 128>>>(out);
}